// round 1
// baseline (speedup 1.0000x reference)
#include <cuda_runtime.h>
#include <cstdint>

#define SEQ   2048
#define EMB   768
#define NH    12
#define HD    64
#define BATCH 2
#define MROWS (BATCH * SEQ)   // 4096

// ---------------- scratch (static device arrays; no allocation) ----------------
__device__ float g_q[BATCH * NH * SEQ * HD];   // [b*NH+h][n][d]
__device__ float g_k[BATCH * NH * SEQ * HD];
__device__ float g_v[BATCH * NH * SEQ * HD];
__device__ float g_ao[BATCH * SEQ * EMB];      // attention output, [b][n][emb]

// =================================================================
// GEMM: C = (A @ W^T + bias) * scale
// A: [M=4096, K=768] row-major, W: [N, K] row-major (torch Linear weight).
// remap=1: scatter output into [b, h, n, d] head-major layout.
// =================================================================
#define GBM 128
#define GBN 128
#define GBK 16
#define GST (GBM + 4)   // padded shared stride

__device__ __forceinline__ void gemm_tile_body(
    const float* __restrict__ A, const float* __restrict__ W,
    const float* __restrict__ bias, float* __restrict__ C,
    int m0, int n0, float scale, int remap)
{
    __shared__ float As[GBK][GST];
    __shared__ float Bs[GBK][GST];

    const int tid = threadIdx.x;
    const int ty = tid >> 4, tx = tid & 15;

    float acc[8][8];
#pragma unroll
    for (int i = 0; i < 8; i++)
#pragma unroll
        for (int j = 0; j < 8; j++) acc[i][j] = 0.f;

    for (int k0 = 0; k0 < EMB; k0 += GBK) {
        // 128 rows x 16 cols per tile = 512 float4; 256 threads -> 2 each
#pragma unroll
        for (int it = 0; it < 2; it++) {
            int e = it * 256 + tid;
            int row = e >> 2;
            int c4 = (e & 3) * 4;
            float4 va = *(const float4*)&A[(size_t)(m0 + row) * EMB + k0 + c4];
            As[c4 + 0][row] = va.x; As[c4 + 1][row] = va.y;
            As[c4 + 2][row] = va.z; As[c4 + 3][row] = va.w;
            float4 vb = *(const float4*)&W[(size_t)(n0 + row) * EMB + k0 + c4];
            Bs[c4 + 0][row] = vb.x; Bs[c4 + 1][row] = vb.y;
            Bs[c4 + 2][row] = vb.z; Bs[c4 + 3][row] = vb.w;
        }
        __syncthreads();

#pragma unroll
        for (int k = 0; k < GBK; k++) {
            float a[8], b[8];
            *(float4*)&a[0] = *(const float4*)&As[k][ty * 8];
            *(float4*)&a[4] = *(const float4*)&As[k][ty * 8 + 4];
            *(float4*)&b[0] = *(const float4*)&Bs[k][tx * 8];
            *(float4*)&b[4] = *(const float4*)&Bs[k][tx * 8 + 4];
#pragma unroll
            for (int i = 0; i < 8; i++)
#pragma unroll
                for (int j = 0; j < 8; j++)
                    acc[i][j] = fmaf(a[i], b[j], acc[i][j]);
        }
        __syncthreads();
    }

    // epilogue
#pragma unroll
    for (int i = 0; i < 8; i++) {
        int m = m0 + ty * 8 + i;
        int b = m >> 11;           // / 2048
        int s = m & 2047;
#pragma unroll
        for (int j = 0; j < 8; j++) {
            int n = n0 + tx * 8 + j;
            float val = (acc[i][j] + bias[n]) * scale;
            if (remap) {
                int h = n >> 6, d = n & 63;
                C[(((size_t)(b * NH + h)) * SEQ + s) * HD + d] = val;
            } else {
                C[(size_t)m * EMB + n] = val;
            }
        }
    }
}

// Fused QKV: one launch covering all three projections (fills the chip:
// 18x32 = 576 blocks vs 3 launches of 192).
__global__ __launch_bounds__(256) void qkv_gemm(
    const float* __restrict__ x,
    const float* __restrict__ wq, const float* __restrict__ bq,
    const float* __restrict__ wk, const float* __restrict__ bk,
    const float* __restrict__ wv, const float* __restrict__ bv)
{
    int m0 = blockIdx.y * GBM;
    int ng = blockIdx.x * GBN;      // 0..2303
    int sel = ng / EMB;             // 0=q, 1=k, 2=v (GBN=128 divides EMB)
    int n0 = ng - sel * EMB;

    const float* W = (sel == 0) ? wq : (sel == 1) ? wk : wv;
    const float* B = (sel == 0) ? bq : (sel == 1) ? bk : bv;
    float* C = (sel == 0) ? g_q : (sel == 1) ? g_k : g_v;
    float scale = (sel == 0) ? 0.125f : 1.0f;

    gemm_tile_body(x, W, B, C, m0, n0, scale, 1);
}

__global__ __launch_bounds__(256) void out_gemm(
    const float* __restrict__ A, const float* __restrict__ W,
    const float* __restrict__ bias, float* __restrict__ C)
{
    gemm_tile_body(A, W, bias, C, blockIdx.y * GBM, blockIdx.x * GBN, 1.0f, 0);
}

// =================================================================
// Flash attention (causal, online softmax).
// grid: (32 q-tiles, 24 bh). 256 threads = 16x16 grid of 4x4 micro-tiles.
// Shared: Qt[d][r], Kt[d][c] (d-major so QK^T inner loop reads float4
// conflict-free), Vs[c][d] and Ps[r][c] natural for the PV loop.
// =================================================================
#define ABM 64
#define ABN 64
#define AST 68   // padded stride (68*4B = 272B, 16B aligned)

__global__ __launch_bounds__(256) void attn_kernel(
    const float* __restrict__ Q, const float* __restrict__ K,
    const float* __restrict__ V, float* __restrict__ O)
{
    extern __shared__ float smem[];
    float (*Qt)[AST] = (float(*)[AST])(smem);                    // [HD][AST]
    float (*Kt)[AST] = (float(*)[AST])(smem + HD * AST);         // [HD][AST]
    float (*Vs)[AST] = (float(*)[AST])(smem + 2 * HD * AST);     // [ABN][AST]
    float (*Ps)[AST] = (float(*)[AST])(smem + 3 * HD * AST);     // [ABM][AST]

    const int bh = blockIdx.y;
    // heavy (late, causal) q-tiles first for wave balance
    const int qt = gridDim.x - 1 - (int)blockIdx.x;
    const int qbase = qt * ABM;

    const float* Qb = Q + (size_t)bh * SEQ * HD;
    const float* Kb = K + (size_t)bh * SEQ * HD;
    const float* Vb = V + (size_t)bh * SEQ * HD;

    const int tid = threadIdx.x;
    const int tr = tid >> 4, tc = tid & 15;
    const int r0 = tr * 4, c0 = tc * 4;

    // Load Q tile transposed: Qt[d][n]. Mapping keeps warps on one d-group
    // so the transposed smem stores are conflict-free.
#pragma unroll
    for (int it = 0; it < 4; it++) {
        int e = it * 256 + tid;         // 0..1023
        int d4 = (e >> 6) * 4;          // 0,4,...,60
        int n = e & 63;
        float4 v = *(const float4*)&Qb[(size_t)(qbase + n) * HD + d4];
        Qt[d4 + 0][n] = v.x; Qt[d4 + 1][n] = v.y;
        Qt[d4 + 2][n] = v.z; Qt[d4 + 3][n] = v.w;
    }

    float m_i[4], l_i[4], o[4][4];
#pragma unroll
    for (int i = 0; i < 4; i++) {
        m_i[i] = -1e30f;
        l_i[i] = 0.f;
#pragma unroll
        for (int j = 0; j < 4; j++) o[i][j] = 0.f;
    }

    for (int kt = 0; kt <= qt; kt++) {
        const int kbase = kt * ABN;
        __syncthreads();   // previous iteration fully done (Kt/Vs/Ps reusable)

        // K transposed (Kt[d][c]) + V natural (Vs[c][d])
#pragma unroll
        for (int it = 0; it < 4; it++) {
            int e = it * 256 + tid;
            int d4 = (e >> 6) * 4;
            int n = e & 63;
            float4 kv = *(const float4*)&Kb[(size_t)(kbase + n) * HD + d4];
            Kt[d4 + 0][n] = kv.x; Kt[d4 + 1][n] = kv.y;
            Kt[d4 + 2][n] = kv.z; Kt[d4 + 3][n] = kv.w;
            int e2 = it * 256 + tid;
            int n2 = e2 >> 4;            // coalesced mapping for V
            int d42 = (e2 & 15) * 4;
            float4 vv = *(const float4*)&Vb[(size_t)(kbase + n2) * HD + d42];
            *(float4*)&Vs[n2][d42] = vv;
        }
        __syncthreads();

        // ---- S = Q K^T (4x4 per thread) ----
        float s[4][4];
#pragma unroll
        for (int i = 0; i < 4; i++)
#pragma unroll
            for (int j = 0; j < 4; j++) s[i][j] = 0.f;

#pragma unroll 8
        for (int d = 0; d < HD; d++) {
            float4 a = *(const float4*)&Qt[d][r0];
            float4 b = *(const float4*)&Kt[d][c0];
            float av[4] = {a.x, a.y, a.z, a.w};
            float bv[4] = {b.x, b.y, b.z, b.w};
#pragma unroll
            for (int i = 0; i < 4; i++)
#pragma unroll
                for (int j = 0; j < 4; j++)
                    s[i][j] = fmaf(av[i], bv[j], s[i][j]);
        }

        // causal mask on the diagonal tile (kbase == qbase there)
        if (kt == qt) {
#pragma unroll
            for (int i = 0; i < 4; i++)
#pragma unroll
                for (int j = 0; j < 4; j++)
                    if (c0 + j > r0 + i) s[i][j] = -1e30f;
        }

        // ---- online softmax (row group = 16 lanes sharing tr) ----
#pragma unroll
        for (int i = 0; i < 4; i++) {
            float rm = fmaxf(fmaxf(s[i][0], s[i][1]), fmaxf(s[i][2], s[i][3]));
#pragma unroll
            for (int off = 1; off < 16; off <<= 1)
                rm = fmaxf(rm, __shfl_xor_sync(0xffffffffu, rm, off));
            float mn = fmaxf(m_i[i], rm);
            float corr = __expf(m_i[i] - mn);
            m_i[i] = mn;
            float rs = 0.f;
#pragma unroll
            for (int j = 0; j < 4; j++) {
                s[i][j] = __expf(s[i][j] - mn);
                rs += s[i][j];
            }
#pragma unroll
            for (int off = 1; off < 16; off <<= 1)
                rs += __shfl_xor_sync(0xffffffffu, rs, off);
            l_i[i] = l_i[i] * corr + rs;
#pragma unroll
            for (int j = 0; j < 4; j++) o[i][j] *= corr;
        }

        // stage P (no sync needed before: Ps last read before loop-top sync)
#pragma unroll
        for (int i = 0; i < 4; i++)
            *(float4*)&Ps[r0 + i][c0] = make_float4(s[i][0], s[i][1], s[i][2], s[i][3]);
        __syncthreads();

        // ---- O += P @ V ----
#pragma unroll 4
        for (int cc = 0; cc < ABN; cc += 4) {
            float a[4][4];
#pragma unroll
            for (int i = 0; i < 4; i++)
                *(float4*)&a[i][0] = *(const float4*)&Ps[r0 + i][cc];
#pragma unroll
            for (int u = 0; u < 4; u++) {
                float4 bv = *(const float4*)&Vs[cc + u][c0];
                float bb[4] = {bv.x, bv.y, bv.z, bv.w};
#pragma unroll
                for (int i = 0; i < 4; i++)
#pragma unroll
                    for (int j = 0; j < 4; j++)
                        o[i][j] = fmaf(a[i][u], bb[j], o[i][j]);
            }
        }
    }

    // epilogue -> [b, n, emb] so the output GEMM reads a standard matrix
    const int b = bh / NH, h = bh % NH;
#pragma unroll
    for (int i = 0; i < 4; i++) {
        float inv = 1.f / l_i[i];
        int n = qbase + r0 + i;
        float* op = O + ((size_t)b * SEQ + n) * EMB + h * HD + c0;
        *(float4*)op = make_float4(o[i][0] * inv, o[i][1] * inv,
                                   o[i][2] * inv, o[i][3] * inv);
    }
}

// =================================================================
// launch
// =================================================================
extern "C" void kernel_launch(void* const* d_in, const int* in_sizes, int n_in,
                              void* d_out, int out_size)
{
    const float* x    = (const float*)d_in[0];
    const float* wq_w = (const float*)d_in[1];
    const float* wq_b = (const float*)d_in[2];
    const float* wk_w = (const float*)d_in[3];
    const float* wk_b = (const float*)d_in[4];
    const float* wv_w = (const float*)d_in[5];
    const float* wv_b = (const float*)d_in[6];
    const float* wo_w = (const float*)d_in[7];
    const float* wo_b = (const float*)d_in[8];
    float* out = (float*)d_out;

    float *q, *k, *v, *ao;
    cudaGetSymbolAddress((void**)&q, g_q);
    cudaGetSymbolAddress((void**)&k, g_k);
    cudaGetSymbolAddress((void**)&v, g_v);
    cudaGetSymbolAddress((void**)&ao, g_ao);

    const int attn_smem = 4 * HD * AST * (int)sizeof(float);   // ~68 KB
    cudaFuncSetAttribute(attn_kernel,
                         cudaFuncAttributeMaxDynamicSharedMemorySize, attn_smem);

    // fused QKV projection: N = 3*768 = 2304 -> grid (18, 32) = 576 blocks
    dim3 gqkv(3 * EMB / GBN, MROWS / GBM);
    qkv_gemm<<<gqkv, 256>>>(x, wq_w, wq_b, wk_w, wk_b, wv_w, wv_b);

    // attention: (32 q-tiles, 24 batch*heads)
    dim3 ga(SEQ / ABM, BATCH * NH);
    attn_kernel<<<ga, 256, attn_smem>>>(q, k, v, ao);

    // output projection
    dim3 go(EMB / GBN, MROWS / GBM);
    out_gemm<<<go, 256>>>(ao, wo_w, wo_b, out);
}